// round 10
// baseline (speedup 1.0000x reference)
#include <cuda_runtime.h>
#include <cuda_bf16.h>
#include <math.h>
#include <stdint.h>

#define BATCH 128
#define NOUT  10
#define NIN   1152
#define DOUT  16
#define DIN   8
#define H1    512
#define H2    1024
#define PIX   784
#define BN    (BATCH*NOUT)   // 1280
#define NCB2  13             // gemm2 column blocks = ceil(784/64)

// ---- scratch (device globals; no allocations allowed) ----
__device__ float g_hat[(size_t)BATCH*NOUT*NIN*DOUT];  // 94.4 MB
__device__ float g_bcoef[(size_t)BATCH*NOUT*NIN];
__device__ float g_c[(size_t)BATCH*NOUT*NIN];
__device__ float g_outcaps[BN*DOUT];
__device__ float g_recon[(size_t)BN*PIX];
__device__ float g_rsp[NCB2*BN];     // rscore partials [colblk][row]

// hi/lo bf16 split operands
__device__ __nv_bfloat16 g_W2h[(size_t)H1*H2], g_W2l[(size_t)H1*H2];
__device__ __nv_bfloat16 g_W3h[(size_t)H2*PIX], g_W3l[(size_t)H2*PIX];
__device__ __nv_bfloat16 g_h1h[(size_t)BN*H1], g_h1l[(size_t)BN*H1];
__device__ __nv_bfloat16 g_h2h[(size_t)BN*H2], g_h2l[(size_t)BN*H2];

__device__ __forceinline__ uint32_t sptr(const void* p) {
    return (uint32_t)__cvta_generic_to_shared(p);
}

// =======================================================================
// Tiled hat: block = (n, 32 k's, 64 b's), dynamic smem staging.
// hat[b,n,k,o] = sum_i weight[n,k,o,i] * incaps[b,k,i]
// =======================================================================
#define HB 64
#define HK 32
#define WS_STRIDE   132
#define INCS_STRIDE 520
#define HAT_SMEM ((HK*WS_STRIDE + HK*INCS_STRIDE) * 4)

__global__ void __launch_bounds__(256) k_hat2(
        const float* __restrict__ incaps, const float* __restrict__ weight) {
    extern __shared__ float hsm[];
    float* ws   = hsm;                     // [k][o*8+i] stride WS_STRIDE
    float* incs = hsm + HK*WS_STRIDE;      // [k][b*8+i] stride INCS_STRIDE
    const int n  = blockIdx.z;
    const int kc = blockIdx.x * HK;
    const int bc = blockIdx.y * HB;
    const int tid = threadIdx.x;

    for (int u = tid; u < HK*16*2; u += 256) {
        int k = u >> 5, r = u & 31, o = r >> 1, half = r & 1;
        float4 v = *(const float4*)(weight +
            ((size_t)((n*NIN + kc + k)*16 + o))*8 + half*4);
        *(float4*)&ws[k*WS_STRIDE + o*8 + half*4] = v;
    }
    for (int u = tid; u < HB*HK*2; u += 256) {
        int b = u >> 6, r = u & 63, k = r >> 1, half = r & 1;
        float4 v = *(const float4*)(incaps +
            ((size_t)(bc + b)*NIN + kc + k)*8 + half*4);
        *(float4*)&incs[k*INCS_STRIDE + b*8 + half*4] = v;
    }
    __syncthreads();

    const int q   = tid & 3;
    const int k_l = (tid >> 2) & 31;
    const int bh  = tid >> 7;

    float w[4][8];
#pragma unroll
    for (int o2 = 0; o2 < 4; o2++) {
        *(float4*)&w[o2][0] = *(float4*)&ws[k_l*WS_STRIDE + (q*4 + o2)*8];
        *(float4*)&w[o2][4] = *(float4*)&ws[k_l*WS_STRIDE + (q*4 + o2)*8 + 4];
    }

#pragma unroll 4
    for (int bi = 0; bi < 32; bi++) {
        int b = bh*32 + bi;
        float x[8];
        *(float4*)&x[0] = *(float4*)&incs[k_l*INCS_STRIDE + b*8];
        *(float4*)&x[4] = *(float4*)&incs[k_l*INCS_STRIDE + b*8 + 4];
        float4 o4;
        o4.x = w[0][0]*x[0]+w[0][1]*x[1]+w[0][2]*x[2]+w[0][3]*x[3]
             + w[0][4]*x[4]+w[0][5]*x[5]+w[0][6]*x[6]+w[0][7]*x[7];
        o4.y = w[1][0]*x[0]+w[1][1]*x[1]+w[1][2]*x[2]+w[1][3]*x[3]
             + w[1][4]*x[4]+w[1][5]*x[5]+w[1][6]*x[6]+w[1][7]*x[7];
        o4.z = w[2][0]*x[0]+w[2][1]*x[1]+w[2][2]*x[2]+w[2][3]*x[3]
             + w[2][4]*x[4]+w[2][5]*x[5]+w[2][6]*x[6]+w[2][7]*x[7];
        o4.w = w[3][0]*x[0]+w[3][1]*x[1]+w[3][2]*x[2]+w[3][3]*x[3]
             + w[3][4]*x[4]+w[3][5]*x[5]+w[3][6]*x[6]+w[3][7]*x[7];
        *(float4*)(g_hat +
            (((size_t)(bc+b)*NOUT + n)*NIN + kc + k_l)*16 + q*4) = o4;
    }
}

// ---- split W2 and W3 (concatenated) fp32 -> bf16 hi/lo ----
__global__ void k_split2(const float* __restrict__ W2, const float* __restrict__ W3) {
    int i = blockIdx.x * blockDim.x + threadIdx.x;
    const int n2 = H1*H2;
    const int nt = n2 + H2*PIX;
    if (i >= nt) return;
    float v; __nv_bfloat16 *ph, *pl; int j;
    if (i < n2) { v = W2[i]; j = i;       ph = g_W2h; pl = g_W2l; }
    else        { j = i - n2; v = W3[j];  ph = g_W3h; pl = g_W3l; }
    __nv_bfloat16 h = __float2bfloat16(v);
    ph[j] = h;
    pl[j] = __float2bfloat16(v - __bfloat162float(h));
}

// =======================================================================
// Fused routing + h1: one pass over hat. Block = one (b,n), 384 threads.
// Computes r = scale_coef(rscore) inline from g_rsp partials.
// hat tile staged to smem fp32 (only if do_b) for the bcoef pass.
// If do_b: also computes h1 = relu(outcaps @ W1-slice + b1) -> bf16 hi/lo.
// =======================================================================
#define RT_THREADS 384
#define RT_SMEM (NIN*DOUT*4)    // 73728 B fp32 staging

__global__ void __launch_bounds__(RT_THREADS) k_routing2(
        int use_rc, int do_b, float* __restrict__ out_vec,
        const float* __restrict__ W1, const float* __restrict__ b1) {
    extern __shared__ float4 tile4[];        // [NIN*4]
    __shared__ float red[12*16];
    __shared__ float s_oc[16];
    __shared__ float s_rglob;

    const int bn   = blockIdx.x;
    const int tid  = threadIdx.x;
    const int lane = tid & 31, warp = tid >> 5;
    const int q    = tid & 3;                // o-quad
    const int krow = tid >> 2;               // 0..95
    const float* hat = g_hat + (size_t)bn * NIN * DOUT;

    if (use_rc) {
        if (tid == 0) {
            int b = bn / NOUT, n = bn % NOUT;
            float rs[NOUT];
#pragma unroll
            for (int m = 0; m < NOUT; m++) {
                float s = 0.f;
#pragma unroll
                for (int cb = 0; cb < NCB2; cb++) s += g_rsp[cb*BN + b*NOUT + m];
                rs[m] = -s;
            }
            float mn = 1e30f, mx = -1e30f;
#pragma unroll
            for (int m = 0; m < 9; m++) { mn = fminf(mn, rs[m]); mx = fmaxf(mx, rs[m]); }
            float denom = fmaxf(mx - mn, 1e-6f);
            s_rglob = (n == 9) ? 0.5f : fmaxf((rs[n]-mn)/denom, 0.5f);
        }
        __syncthreads();
    }
    const float rglob = use_rc ? s_rglob : 1.0f;

    float rcv[12];
    if (use_rc) {
        const float* cb = g_c + (size_t)bn * NIN;
#pragma unroll
        for (int i = 0; i < 12; i++) rcv[i] = cb[krow + 96*i] * rglob;
    } else {
#pragma unroll
        for (int i = 0; i < 12; i++) rcv[i] = 1.0f;
    }

    float4 v[12];
#pragma unroll
    for (int i = 0; i < 12; i++)
        v[i] = *(const float4*)(hat + ((size_t)(krow + 96*i) * 16) + q * 4);

    float a0 = 0.f, a1 = 0.f, a2 = 0.f, a3 = 0.f;
#pragma unroll
    for (int i = 0; i < 12; i++) {
        if (do_b) tile4[tid + 384*i] = v[i];
        a0 += rcv[i] * v[i].x; a1 += rcv[i] * v[i].y;
        a2 += rcv[i] * v[i].z; a3 += rcv[i] * v[i].w;
    }

#pragma unroll
    for (int m = 4; m <= 16; m <<= 1) {
        a0 += __shfl_xor_sync(0xffffffffu, a0, m);
        a1 += __shfl_xor_sync(0xffffffffu, a1, m);
        a2 += __shfl_xor_sync(0xffffffffu, a2, m);
        a3 += __shfl_xor_sync(0xffffffffu, a3, m);
    }
    if (lane < 4) {
        red[warp*16 + lane*4 + 0] = a0;
        red[warp*16 + lane*4 + 1] = a1;
        red[warp*16 + lane*4 + 2] = a2;
        red[warp*16 + lane*4 + 3] = a3;
    }
    __syncthreads();

    if (tid == 0) {
        float tot[16];
        float n2 = 0.f;
#pragma unroll
        for (int o = 0; o < 16; o++) {
            float s = 0.f;
#pragma unroll
            for (int w = 0; w < 12; w++) s += red[w*16 + o];
            tot[o] = s; n2 += s*s;
        }
        float nrm   = sqrtf(n2);
        float scale = n2 / (1.f + n2) / (nrm + 1e-8f);
        float* dst = out_vec ? out_vec : g_outcaps;
#pragma unroll
        for (int o = 0; o < 16; o++) {
            float vv = scale * tot[o];
            s_oc[o] = vv;
            dst[(size_t)bn*16 + o] = vv;
        }
    }
    __syncthreads();
    if (!do_b) return;

    // bcoef from smem-staged tile
    const float oc0 = s_oc[q*4+0], oc1 = s_oc[q*4+1];
    const float oc2 = s_oc[q*4+2], oc3 = s_oc[q*4+3];
    float* bc = g_bcoef + (size_t)bn * NIN;
#pragma unroll
    for (int i = 0; i < 12; i++) {
        float4 h = tile4[tid + 384*i];
        float p = h.x*oc0 + h.y*oc1 + h.z*oc2 + h.w*oc3;
        p += __shfl_xor_sync(0xffffffffu, p, 1);
        p += __shfl_xor_sync(0xffffffffu, p, 2);
        if (q == 0) bc[krow + 96*i] = p;
    }

    // fused h1 = relu(oc @ W1[m-slice] + b1) -> bf16 hi/lo
    {
        const int m = bn % NOUT;
        for (int j = tid; j < H1; j += RT_THREADS) {
            float s = b1[j];
#pragma unroll
            for (int d = 0; d < 16; d++)
                s += s_oc[d] * W1[(size_t)(m*16 + d)*H1 + j];
            float vv = fmaxf(s, 0.f);
            __nv_bfloat16 h = __float2bfloat16(vv);
            g_h1h[(size_t)bn*H1 + j] = h;
            g_h1l[(size_t)bn*H1 + j] = __float2bfloat16(vv - __bfloat162float(h));
        }
    }
}

// ---- c = scale_coef(bcoef) over axis n (first 9), bg slot -> 0.5 ----
__global__ void __launch_bounds__(256) k_scale_c() {
    int idx = blockIdx.x * 256 + threadIdx.x;
    if (idx >= BATCH * NIN) return;
    int b = idx / NIN, k = idx % NIN;
    float v[9];
    float mn = 1e30f, mx = -1e30f;
#pragma unroll
    for (int n = 0; n < 9; n++) {
        float t = g_bcoef[((size_t)b*NOUT + n)*NIN + k];
        v[n] = t; mn = fminf(mn, t); mx = fmaxf(mx, t);
    }
    float denom = fmaxf(mx - mn, 1e-6f);
#pragma unroll
    for (int n = 0; n < 9; n++)
        g_c[((size_t)b*NOUT + n)*NIN + k] = fmaxf((v[n]-mn)/denom, 0.5f);
    g_c[((size_t)b*NOUT + 9)*NIN + k] = 0.5f;
}

// =======================================================================
// Tensor-core GEMM, bf16 hi/lo 3-term compensation (~fp32 precision).
// BM=64, BN=64, BK=32, 128 threads (4 warps, 2x2 grid of 32x32 warp tiles).
// ~39 KB smem -> multi-CTA/SM co-residency (kills wave quantization).
// EPI=1: relu -> Ch/Cl bf16 split.
// EPI=2: sigmoid -> Cf fp32 + fused rscore partials to g_rsp (fixed order).
// =======================================================================
#define MMA_BF16(d, a, b0r, b1r)                                            \
    asm volatile(                                                           \
        "mma.sync.aligned.m16n8k16.row.col.f32.bf16.bf16.f32 "              \
        "{%0,%1,%2,%3},{%4,%5,%6,%7},{%8,%9},{%0,%1,%2,%3};"                \
        : "+f"((d)[0]), "+f"((d)[1]), "+f"((d)[2]), "+f"((d)[3])            \
        : "r"((a)[0]), "r"((a)[1]), "r"((a)[2]), "r"((a)[3]),               \
          "r"(b0r), "r"(b1r))

#define LDSM_X4(r, addr)                                                    \
    asm volatile("ldmatrix.sync.aligned.m8n8.x4.shared.b16 {%0,%1,%2,%3}, [%4];" \
        : "=r"((r)[0]), "=r"((r)[1]), "=r"((r)[2]), "=r"((r)[3]) : "r"(addr))

#define LDSM_X4T(r, addr)                                                   \
    asm volatile("ldmatrix.sync.aligned.m8n8.x4.trans.shared.b16 {%0,%1,%2,%3}, [%4];" \
        : "=r"((r)[0]), "=r"((r)[1]), "=r"((r)[2]), "=r"((r)[3]) : "r"(addr))

#define AS_STRIDE 40   // 32 + 8 pad
#define BS_STRIDE 72   // 64 + 8 pad
#define GEMM_SMEM ((2*2*64*AS_STRIDE + 2*2*32*BS_STRIDE) * 2)

template <int EPI>
__global__ void __launch_bounds__(128) k_gemm_tc(
    const __nv_bfloat16* __restrict__ Ah, const __nv_bfloat16* __restrict__ Al,
    const __nv_bfloat16* __restrict__ Bh, const __nv_bfloat16* __restrict__ Bl,
    const float* __restrict__ bias,
    float* __restrict__ Cf, __nv_bfloat16* __restrict__ Ch,
    __nv_bfloat16* __restrict__ Cl,
    const float* __restrict__ xin,          // EPI==2 only
    int N, int Kd)
{
    extern __shared__ char smem_raw[];
    __nv_bfloat16* As = (__nv_bfloat16*)smem_raw;           // [2][2][64][40]
    __nv_bfloat16* Bs = As + 2*2*64*AS_STRIDE;               // [2][2][32][72]
    __shared__ float s_rs[64][2];

    const int tid  = threadIdx.x;
    const int lane = tid & 31, warp = tid >> 5;
    const int row0 = blockIdx.y * 64, col0 = blockIdx.x * 64;
    const int m0 = (warp & 1) * 32, n0 = (warp >> 1) * 32;

    const int arow = tid >> 1, aks = (tid & 1) * 16;   // 64 rows x 2 k-halves
    const int bkr  = tid >> 2, bnc = (tid & 3) * 16;   // 32 rows x 4 col-groups

    float acc[2][4][4];
#pragma unroll
    for (int i = 0; i < 2; i++)
#pragma unroll
        for (int j = 0; j < 4; j++)
#pragma unroll
            for (int q = 0; q < 4; q++) acc[i][j][q] = 0.f;

    const int S = Kd >> 5;
    uint4 pA[4], pB[4];

    const __nv_bfloat16* Abase_h = Ah + (size_t)(row0 + arow) * Kd + aks;
    const __nv_bfloat16* Abase_l = Al + (size_t)(row0 + arow) * Kd + aks;
    const int bcol = col0 + bnc;

    auto loadS = [&](int s) {
        const __nv_bfloat16* pa = Abase_h + s * 32;
        pA[0] = *(const uint4*)pa; pA[1] = *(const uint4*)(pa + 8);
        const __nv_bfloat16* pl = Abase_l + s * 32;
        pA[2] = *(const uint4*)pl; pA[3] = *(const uint4*)(pl + 8);
        const __nv_bfloat16* pbh = Bh + (size_t)(s * 32 + bkr) * N + bcol;
        const __nv_bfloat16* pbl = Bl + (size_t)(s * 32 + bkr) * N + bcol;
#pragma unroll
        for (int g = 0; g < 2; g++) {
            if (bcol + g*8 + 7 < N) {
                pB[g]   = *(const uint4*)(pbh + g*8);
                pB[2+g] = *(const uint4*)(pbl + g*8);
            } else {
                __nv_bfloat16 th[8], tl[8];
#pragma unroll
                for (int j = 0; j < 8; j++) {
                    bool ok = (bcol + g*8 + j < N);
                    th[j] = ok ? pbh[g*8 + j] : __nv_bfloat16(0.f);
                    tl[j] = ok ? pbl[g*8 + j] : __nv_bfloat16(0.f);
                }
                pB[g]   = *(const uint4*)th;
                pB[2+g] = *(const uint4*)tl;
            }
        }
    };
    auto storeS = [&](int buf) {
        *(uint4*)&As[((buf*2 + 0)*64 + arow)*AS_STRIDE + aks]     = pA[0];
        *(uint4*)&As[((buf*2 + 0)*64 + arow)*AS_STRIDE + aks + 8] = pA[1];
        *(uint4*)&As[((buf*2 + 1)*64 + arow)*AS_STRIDE + aks]     = pA[2];
        *(uint4*)&As[((buf*2 + 1)*64 + arow)*AS_STRIDE + aks + 8] = pA[3];
        *(uint4*)&Bs[((buf*2 + 0)*32 + bkr)*BS_STRIDE + bnc]     = pB[0];
        *(uint4*)&Bs[((buf*2 + 0)*32 + bkr)*BS_STRIDE + bnc + 8] = pB[1];
        *(uint4*)&Bs[((buf*2 + 1)*32 + bkr)*BS_STRIDE + bnc]     = pB[2];
        *(uint4*)&Bs[((buf*2 + 1)*32 + bkr)*BS_STRIDE + bnc + 8] = pB[3];
    };

    const int afr = m0 + (lane & 15);
    const int afc = (lane >> 4) * 8;
    const int bfr = (lane & 15);
    const int bfc = n0 + (lane >> 4) * 8;

    loadS(0); storeS(0);
    __syncthreads();

    for (int s = 0; s < S; s++) {
        const int cur = s & 1;
        if (s + 1 < S) loadS(s + 1);

#pragma unroll
        for (int kf = 0; kf < 2; kf++) {
            uint32_t ahr[2][4], alr[2][4], bhr[2][4], blr[2][4];
#pragma unroll
            for (int im = 0; im < 2; im++) {
                uint32_t ad_h = sptr(&As[((cur*2+0)*64 + afr + im*16)*AS_STRIDE + kf*16 + afc]);
                LDSM_X4(ahr[im], ad_h);
                uint32_t ad_l = sptr(&As[((cur*2+1)*64 + afr + im*16)*AS_STRIDE + kf*16 + afc]);
                LDSM_X4(alr[im], ad_l);
            }
#pragma unroll
            for (int nb = 0; nb < 2; nb++) {
                uint32_t bd_h = sptr(&Bs[((cur*2+0)*32 + kf*16 + bfr)*BS_STRIDE + bfc + nb*16]);
                LDSM_X4T(bhr[nb], bd_h);
                uint32_t bd_l = sptr(&Bs[((cur*2+1)*32 + kf*16 + bfr)*BS_STRIDE + bfc + nb*16]);
                LDSM_X4T(blr[nb], bd_l);
            }
#pragma unroll
            for (int im = 0; im < 2; im++)
#pragma unroll
                for (int in = 0; in < 4; in++) {
                    const int nb = in >> 1, ns = in & 1;
                    uint32_t b0h = bhr[nb][ns*2], b1h = bhr[nb][ns*2+1];
                    uint32_t b0l = blr[nb][ns*2], b1l = blr[nb][ns*2+1];
                    MMA_BF16(acc[im][in], ahr[im], b0h, b1h);
                    MMA_BF16(acc[im][in], ahr[im], b0l, b1l);
                    MMA_BF16(acc[im][in], alr[im], b0h, b1h);
                }
        }

        if (s + 1 < S) storeS((s + 1) & 1);
        __syncthreads();
    }

    float rp[2][2] = {{0.f, 0.f}, {0.f, 0.f}};   // [im][half] rscore partials

#pragma unroll
    for (int im = 0; im < 2; im++)
#pragma unroll
        for (int in = 0; in < 4; in++) {
            int r = row0 + m0 + im*16 + (lane >> 2);
            int c = col0 + n0 + in*8 + (lane & 3) * 2;
            float bi0 = (c < N)     ? bias[c]     : 0.f;
            float bi1 = (c + 1 < N) ? bias[c + 1] : 0.f;
#pragma unroll
            for (int half = 0; half < 2; half++) {
                int rr = r + half * 8;
                float v0 = acc[im][in][half*2 + 0] + bi0;
                float v1 = acc[im][in][half*2 + 1] + bi1;
                if (EPI == 1) {
                    v0 = fmaxf(v0, 0.f); v1 = fmaxf(v1, 0.f);
                    __nv_bfloat16 h0 = __float2bfloat16(v0);
                    __nv_bfloat16 h1 = __float2bfloat16(v1);
                    __nv_bfloat162 hh; hh.x = h0; hh.y = h1;
                    *(__nv_bfloat162*)&Ch[(size_t)rr*N + c] = hh;
                    __nv_bfloat162 ll;
                    ll.x = __float2bfloat16(v0 - __bfloat162float(h0));
                    ll.y = __float2bfloat16(v1 - __bfloat162float(h1));
                    *(__nv_bfloat162*)&Cl[(size_t)rr*N + c] = ll;
                } else {
                    v0 = 1.f / (1.f + __expf(-v0));
                    v1 = 1.f / (1.f + __expf(-v1));
                    int b = rr / NOUT;
                    if (c < N) {
                        Cf[(size_t)rr*N + c] = v0;
                        float d = xin[(size_t)b*PIX + c] - v0;
                        rp[im][half] += d * d;
                    }
                    if (c + 1 < N) {
                        Cf[(size_t)rr*N + c + 1] = v1;
                        float d = xin[(size_t)b*PIX + c + 1] - v1;
                        rp[im][half] += d * d;
                    }
                }
            }
        }

    if (EPI == 2) {
        // fixed-order reduction: quad shfl -> smem[row][n-half] -> sum
#pragma unroll
        for (int im = 0; im < 2; im++)
#pragma unroll
            for (int half = 0; half < 2; half++) {
                float s = rp[im][half];
                s += __shfl_xor_sync(0xffffffffu, s, 1);
                s += __shfl_xor_sync(0xffffffffu, s, 2);
                if ((lane & 3) == 0)
                    s_rs[m0 + im*16 + half*8 + (lane >> 2)][warp >> 1] = s;
            }
        __syncthreads();
        if (tid < 64)
            g_rsp[blockIdx.x*BN + row0 + tid] = s_rs[tid][0] + s_rs[tid][1];
    }
}

extern "C" void kernel_launch(void* const* d_in, const int* in_sizes, int n_in,
                              void* d_out, int out_size) {
    const float* incaps = (const float*)d_in[0];
    const float* x      = (const float*)d_in[1];
    const float* weight = (const float*)d_in[2];
    const float* W1     = (const float*)d_in[3];
    const float* b1     = (const float*)d_in[4];
    const float* W2     = (const float*)d_in[5];
    const float* b2     = (const float*)d_in[6];
    const float* W3     = (const float*)d_in[7];
    const float* b3     = (const float*)d_in[8];
    float* out = (float*)d_out;

    cudaFuncSetAttribute(k_gemm_tc<1>, cudaFuncAttributeMaxDynamicSharedMemorySize, GEMM_SMEM);
    cudaFuncSetAttribute(k_gemm_tc<2>, cudaFuncAttributeMaxDynamicSharedMemorySize, GEMM_SMEM);
    cudaFuncSetAttribute(k_routing2, cudaFuncAttributeMaxDynamicSharedMemorySize, RT_SMEM);
    cudaFuncSetAttribute(k_hat2, cudaFuncAttributeMaxDynamicSharedMemorySize, HAT_SMEM);

    __nv_bfloat16 *pW2h, *pW2l, *pW3h, *pW3l, *ph1h, *ph1l, *ph2h, *ph2l;
    float *p_recon;
    cudaGetSymbolAddress((void**)&pW2h, g_W2h);
    cudaGetSymbolAddress((void**)&pW2l, g_W2l);
    cudaGetSymbolAddress((void**)&pW3h, g_W3h);
    cudaGetSymbolAddress((void**)&pW3l, g_W3l);
    cudaGetSymbolAddress((void**)&ph1h, g_h1h);
    cudaGetSymbolAddress((void**)&ph1l, g_h1l);
    cudaGetSymbolAddress((void**)&ph2h, g_h2h);
    cudaGetSymbolAddress((void**)&ph2l, g_h2l);
    cudaGetSymbolAddress((void**)&p_recon, g_recon);

    k_hat2<<<dim3(NIN/HK, BATCH/HB, NOUT), 256, HAT_SMEM>>>(incaps, weight);
    k_split2<<<(H1*H2 + H2*PIX + 255)/256, 256>>>(W2, W3);

    for (int it = 0; it < 2; it++) {
        k_routing2<<<BN, RT_THREADS, RT_SMEM>>>(it > 0 ? 1 : 0, 1, nullptr, W1, b1);
        k_scale_c<<<(BATCH*NIN + 255)/256, 256>>>();
        k_gemm_tc<1><<<dim3(H2/64, BN/64), 128, GEMM_SMEM>>>(
            ph1h, ph1l, pW2h, pW2l, b2, nullptr, ph2h, ph2l, nullptr, H2, H1);
        k_gemm_tc<2><<<dim3(NCB2, BN/64), 128, GEMM_SMEM>>>(
            ph2h, ph2l, pW3h, pW3l, b3, p_recon, nullptr, nullptr, x, PIX, H2);
    }
    k_routing2<<<BN, RT_THREADS, 0>>>(1, 0, out, W1, b1);
}

// round 12
// speedup vs baseline: 1.0183x; 1.0183x over previous
#include <cuda_runtime.h>
#include <cuda_bf16.h>
#include <math.h>
#include <stdint.h>

#define BATCH 128
#define NOUT  10
#define NIN   1152
#define DOUT  16
#define DIN   8
#define H1    512
#define H2    1024
#define PIX   784
#define BN    (BATCH*NOUT)   // 1280
#define NCB2  13             // gemm2 column blocks = ceil(784/64)

// ---- PDL primitives ----
#define PDL_WAIT()    asm volatile("griddepcontrol.wait;" ::: "memory")
#define PDL_TRIGGER() asm volatile("griddepcontrol.launch_dependents;" ::: "memory")

// ---- scratch (device globals; no allocations allowed) ----
__device__ float g_hat[(size_t)BATCH*NOUT*NIN*DOUT];  // 94.4 MB
__device__ float g_bcoef[(size_t)BATCH*NOUT*NIN];
__device__ float g_c[(size_t)BATCH*NOUT*NIN];
__device__ float g_outcaps[BN*DOUT];
__device__ float g_recon[(size_t)BN*PIX];
__device__ float g_rsp[NCB2*BN];     // rscore partials [colblk][row]

// hi/lo bf16 split operands
__device__ __nv_bfloat16 g_W2h[(size_t)H1*H2], g_W2l[(size_t)H1*H2];
__device__ __nv_bfloat16 g_W3h[(size_t)H2*PIX], g_W3l[(size_t)H2*PIX];
__device__ __nv_bfloat16 g_h1h[(size_t)BN*H1], g_h1l[(size_t)BN*H1];
__device__ __nv_bfloat16 g_h2h[(size_t)BN*H2], g_h2l[(size_t)BN*H2];

__device__ __forceinline__ uint32_t sptr(const void* p) {
    return (uint32_t)__cvta_generic_to_shared(p);
}

// =======================================================================
// Merged hat + weight-split kernel (independent work, one launch).
// Blocks [0, HAT_BLOCKS): tiled hat. Blocks [HAT_BLOCKS, +SPLIT_BLOCKS): split.
// =======================================================================
#define HB 64
#define HK 32
#define WS_STRIDE   132
#define INCS_STRIDE 520
#define HAT_SMEM ((HK*WS_STRIDE + HK*INCS_STRIDE) * 4)
#define HAT_BLOCKS  ((NIN/HK) * (BATCH/HB) * NOUT)           // 36*2*10 = 720
#define SPLIT_BLOCKS ((H1*H2 + H2*PIX + 255)/256)            // 5184

__global__ void __launch_bounds__(256) k_hat_split(
        const float* __restrict__ incaps, const float* __restrict__ weight,
        const float* __restrict__ W2, const float* __restrict__ W3) {
    const int tid = threadIdx.x;
    if (blockIdx.x >= HAT_BLOCKS) {
        // ---- weight split part ----
        int i = (blockIdx.x - HAT_BLOCKS) * 256 + tid;
        const int n2 = H1*H2;
        const int nt = n2 + H2*PIX;
        if (i < nt) {
            float v; __nv_bfloat16 *ph, *pl; int j;
            if (i < n2) { v = W2[i]; j = i;       ph = g_W2h; pl = g_W2l; }
            else        { j = i - n2; v = W3[j];  ph = g_W3h; pl = g_W3l; }
            __nv_bfloat16 h = __float2bfloat16(v);
            ph[j] = h;
            pl[j] = __float2bfloat16(v - __bfloat162float(h));
        }
        PDL_TRIGGER();
        return;
    }
    // ---- tiled hat part ----
    extern __shared__ float hsm[];
    float* ws   = hsm;                     // [k][o*8+i] stride WS_STRIDE
    float* incs = hsm + HK*WS_STRIDE;      // [k][b*8+i] stride INCS_STRIDE
    const int bid = blockIdx.x;
    const int kc = (bid % 36) * HK;
    const int bc = ((bid / 36) & 1) * HB;
    const int n  = bid / 72;

    for (int u = tid; u < HK*16*2; u += 256) {
        int k = u >> 5, r = u & 31, o = r >> 1, half = r & 1;
        float4 v = *(const float4*)(weight +
            ((size_t)((n*NIN + kc + k)*16 + o))*8 + half*4);
        *(float4*)&ws[k*WS_STRIDE + o*8 + half*4] = v;
    }
    for (int u = tid; u < HB*HK*2; u += 256) {
        int b = u >> 6, r = u & 63, k = r >> 1, half = r & 1;
        float4 v = *(const float4*)(incaps +
            ((size_t)(bc + b)*NIN + kc + k)*8 + half*4);
        *(float4*)&incs[k*INCS_STRIDE + b*8 + half*4] = v;
    }
    __syncthreads();

    const int q   = tid & 3;
    const int k_l = (tid >> 2) & 31;
    const int bh  = tid >> 7;

    float w[4][8];
#pragma unroll
    for (int o2 = 0; o2 < 4; o2++) {
        *(float4*)&w[o2][0] = *(float4*)&ws[k_l*WS_STRIDE + (q*4 + o2)*8];
        *(float4*)&w[o2][4] = *(float4*)&ws[k_l*WS_STRIDE + (q*4 + o2)*8 + 4];
    }

#pragma unroll 4
    for (int bi = 0; bi < 32; bi++) {
        int b = bh*32 + bi;
        float x[8];
        *(float4*)&x[0] = *(float4*)&incs[k_l*INCS_STRIDE + b*8];
        *(float4*)&x[4] = *(float4*)&incs[k_l*INCS_STRIDE + b*8 + 4];
        float4 o4;
        o4.x = w[0][0]*x[0]+w[0][1]*x[1]+w[0][2]*x[2]+w[0][3]*x[3]
             + w[0][4]*x[4]+w[0][5]*x[5]+w[0][6]*x[6]+w[0][7]*x[7];
        o4.y = w[1][0]*x[0]+w[1][1]*x[1]+w[1][2]*x[2]+w[1][3]*x[3]
             + w[1][4]*x[4]+w[1][5]*x[5]+w[1][6]*x[6]+w[1][7]*x[7];
        o4.z = w[2][0]*x[0]+w[2][1]*x[1]+w[2][2]*x[2]+w[2][3]*x[3]
             + w[2][4]*x[4]+w[2][5]*x[5]+w[2][6]*x[6]+w[2][7]*x[7];
        o4.w = w[3][0]*x[0]+w[3][1]*x[1]+w[3][2]*x[2]+w[3][3]*x[3]
             + w[3][4]*x[4]+w[3][5]*x[5]+w[3][6]*x[6]+w[3][7]*x[7];
        *(float4*)(g_hat +
            (((size_t)(bc+b)*NOUT + n)*NIN + kc + k_l)*16 + q*4) = o4;
    }
    PDL_TRIGGER();
}

// =======================================================================
// Fused routing + h1: one pass over hat. Block = one (b,n), 384 threads.
// Computes r = scale_coef(rscore) inline from g_rsp partials.
// hat tile staged to smem fp32 (only if do_b) for the bcoef pass.
// If do_b: also computes h1 = relu(outcaps @ W1-slice + b1) -> bf16 hi/lo.
// =======================================================================
#define RT_THREADS 384
#define RT_SMEM (NIN*DOUT*4)    // 73728 B fp32 staging

__global__ void __launch_bounds__(RT_THREADS) k_routing2(
        int use_rc, int do_b, float* __restrict__ out_vec,
        const float* __restrict__ W1, const float* __restrict__ b1) {
    extern __shared__ float4 tile4[];        // [NIN*4]
    __shared__ float red[12*16];
    __shared__ float s_oc[16];
    __shared__ float s_rglob;

    PDL_WAIT();

    const int bn   = blockIdx.x;
    const int tid  = threadIdx.x;
    const int lane = tid & 31, warp = tid >> 5;
    const int q    = tid & 3;                // o-quad
    const int krow = tid >> 2;               // 0..95
    const float* hat = g_hat + (size_t)bn * NIN * DOUT;

    if (use_rc) {
        if (tid == 0) {
            int b = bn / NOUT, n = bn % NOUT;
            float rs[NOUT];
#pragma unroll
            for (int m = 0; m < NOUT; m++) {
                float s = 0.f;
#pragma unroll
                for (int cb = 0; cb < NCB2; cb++) s += g_rsp[cb*BN + b*NOUT + m];
                rs[m] = -s;
            }
            float mn = 1e30f, mx = -1e30f;
#pragma unroll
            for (int m = 0; m < 9; m++) { mn = fminf(mn, rs[m]); mx = fmaxf(mx, rs[m]); }
            float denom = fmaxf(mx - mn, 1e-6f);
            s_rglob = (n == 9) ? 0.5f : fmaxf((rs[n]-mn)/denom, 0.5f);
        }
        __syncthreads();
    }
    const float rglob = use_rc ? s_rglob : 1.0f;

    float rcv[12];
    if (use_rc) {
        const float* cb = g_c + (size_t)bn * NIN;
#pragma unroll
        for (int i = 0; i < 12; i++) rcv[i] = cb[krow + 96*i] * rglob;
    } else {
#pragma unroll
        for (int i = 0; i < 12; i++) rcv[i] = 1.0f;
    }

    float4 v[12];
#pragma unroll
    for (int i = 0; i < 12; i++)
        v[i] = *(const float4*)(hat + ((size_t)(krow + 96*i) * 16) + q * 4);

    float a0 = 0.f, a1 = 0.f, a2 = 0.f, a3 = 0.f;
#pragma unroll
    for (int i = 0; i < 12; i++) {
        if (do_b) tile4[tid + 384*i] = v[i];
        a0 += rcv[i] * v[i].x; a1 += rcv[i] * v[i].y;
        a2 += rcv[i] * v[i].z; a3 += rcv[i] * v[i].w;
    }

#pragma unroll
    for (int m = 4; m <= 16; m <<= 1) {
        a0 += __shfl_xor_sync(0xffffffffu, a0, m);
        a1 += __shfl_xor_sync(0xffffffffu, a1, m);
        a2 += __shfl_xor_sync(0xffffffffu, a2, m);
        a3 += __shfl_xor_sync(0xffffffffu, a3, m);
    }
    if (lane < 4) {
        red[warp*16 + lane*4 + 0] = a0;
        red[warp*16 + lane*4 + 1] = a1;
        red[warp*16 + lane*4 + 2] = a2;
        red[warp*16 + lane*4 + 3] = a3;
    }
    __syncthreads();

    if (tid == 0) {
        float tot[16];
        float n2 = 0.f;
#pragma unroll
        for (int o = 0; o < 16; o++) {
            float s = 0.f;
#pragma unroll
            for (int w = 0; w < 12; w++) s += red[w*16 + o];
            tot[o] = s; n2 += s*s;
        }
        float nrm   = sqrtf(n2);
        float scale = n2 / (1.f + n2) / (nrm + 1e-8f);
        float* dst = out_vec ? out_vec : g_outcaps;
#pragma unroll
        for (int o = 0; o < 16; o++) {
            float vv = scale * tot[o];
            s_oc[o] = vv;
            dst[(size_t)bn*16 + o] = vv;
        }
    }
    __syncthreads();
    if (!do_b) return;

    // bcoef from smem-staged tile
    const float oc0 = s_oc[q*4+0], oc1 = s_oc[q*4+1];
    const float oc2 = s_oc[q*4+2], oc3 = s_oc[q*4+3];
    float* bc = g_bcoef + (size_t)bn * NIN;
#pragma unroll
    for (int i = 0; i < 12; i++) {
        float4 h = tile4[tid + 384*i];
        float p = h.x*oc0 + h.y*oc1 + h.z*oc2 + h.w*oc3;
        p += __shfl_xor_sync(0xffffffffu, p, 1);
        p += __shfl_xor_sync(0xffffffffu, p, 2);
        if (q == 0) bc[krow + 96*i] = p;
    }

    PDL_TRIGGER();   // scale_c may schedule; it still waits for full completion

    // fused h1 = relu(oc @ W1[m-slice] + b1) -> bf16 hi/lo
    {
        const int m = bn % NOUT;
        for (int j = tid; j < H1; j += RT_THREADS) {
            float s = b1[j];
#pragma unroll
            for (int d = 0; d < 16; d++)
                s += s_oc[d] * W1[(size_t)(m*16 + d)*H1 + j];
            float vv = fmaxf(s, 0.f);
            __nv_bfloat16 h = __float2bfloat16(vv);
            g_h1h[(size_t)bn*H1 + j] = h;
            g_h1l[(size_t)bn*H1 + j] = __float2bfloat16(vv - __bfloat162float(h));
        }
    }
}

// ---- c = scale_coef(bcoef) over axis n (first 9), bg slot -> 0.5 ----
__global__ void __launch_bounds__(256) k_scale_c() {
    PDL_WAIT();
    int idx = blockIdx.x * 256 + threadIdx.x;
    if (idx < BATCH * NIN) {
        int b = idx / NIN, k = idx % NIN;
        float v[9];
        float mn = 1e30f, mx = -1e30f;
#pragma unroll
        for (int n = 0; n < 9; n++) {
            float t = g_bcoef[((size_t)b*NOUT + n)*NIN + k];
            v[n] = t; mn = fminf(mn, t); mx = fmaxf(mx, t);
        }
        float denom = fmaxf(mx - mn, 1e-6f);
#pragma unroll
        for (int n = 0; n < 9; n++)
            g_c[((size_t)b*NOUT + n)*NIN + k] = fmaxf((v[n]-mn)/denom, 0.5f);
        g_c[((size_t)b*NOUT + 9)*NIN + k] = 0.5f;
    }
    PDL_TRIGGER();
}

// =======================================================================
// Tensor-core GEMM, bf16 hi/lo 3-term compensation (~fp32 precision).
// BM=64, BN=64, BK=32, 128 threads. PDL: B slab-0 (static weights) loads
// BEFORE griddepcontrol.wait; A (dependent activations) after.
// EPI=1: relu -> Ch/Cl bf16 split.
// EPI=2: sigmoid -> Cf fp32 + fused rscore partials to g_rsp (fixed order).
// =======================================================================
#define MMA_BF16(d, a, b0r, b1r)                                            \
    asm volatile(                                                           \
        "mma.sync.aligned.m16n8k16.row.col.f32.bf16.bf16.f32 "              \
        "{%0,%1,%2,%3},{%4,%5,%6,%7},{%8,%9},{%0,%1,%2,%3};"                \
        : "+f"((d)[0]), "+f"((d)[1]), "+f"((d)[2]), "+f"((d)[3])            \
        : "r"((a)[0]), "r"((a)[1]), "r"((a)[2]), "r"((a)[3]),               \
          "r"(b0r), "r"(b1r))

#define LDSM_X4(r, addr)                                                    \
    asm volatile("ldmatrix.sync.aligned.m8n8.x4.shared.b16 {%0,%1,%2,%3}, [%4];" \
        : "=r"((r)[0]), "=r"((r)[1]), "=r"((r)[2]), "=r"((r)[3]) : "r"(addr))

#define LDSM_X4T(r, addr)                                                   \
    asm volatile("ldmatrix.sync.aligned.m8n8.x4.trans.shared.b16 {%0,%1,%2,%3}, [%4];" \
        : "=r"((r)[0]), "=r"((r)[1]), "=r"((r)[2]), "=r"((r)[3]) : "r"(addr))

#define AS_STRIDE 40   // 32 + 8 pad
#define BS_STRIDE 72   // 64 + 8 pad
#define GEMM_SMEM ((2*2*64*AS_STRIDE + 2*2*32*BS_STRIDE) * 2)

template <int EPI>
__global__ void __launch_bounds__(128) k_gemm_tc(
    const __nv_bfloat16* __restrict__ Ah, const __nv_bfloat16* __restrict__ Al,
    const __nv_bfloat16* __restrict__ Bh, const __nv_bfloat16* __restrict__ Bl,
    const float* __restrict__ bias,
    float* __restrict__ Cf, __nv_bfloat16* __restrict__ Ch,
    __nv_bfloat16* __restrict__ Cl,
    const float* __restrict__ xin,          // EPI==2 only
    int N, int Kd)
{
    extern __shared__ char smem_raw[];
    __nv_bfloat16* As = (__nv_bfloat16*)smem_raw;           // [2][2][64][40]
    __nv_bfloat16* Bs = As + 2*2*64*AS_STRIDE;               // [2][2][32][72]
    __shared__ float s_rs[64][2];

    const int tid  = threadIdx.x;
    const int lane = tid & 31, warp = tid >> 5;
    const int row0 = blockIdx.y * 64, col0 = blockIdx.x * 64;
    const int m0 = (warp & 1) * 32, n0 = (warp >> 1) * 32;

    const int arow = tid >> 1, aks = (tid & 1) * 16;   // 64 rows x 2 k-halves
    const int bkr  = tid >> 2, bnc = (tid & 3) * 16;   // 32 rows x 4 col-groups

    float acc[2][4][4];
#pragma unroll
    for (int i = 0; i < 2; i++)
#pragma unroll
        for (int j = 0; j < 4; j++)
#pragma unroll
            for (int q = 0; q < 4; q++) acc[i][j][q] = 0.f;

    const int S = Kd >> 5;
    uint4 pA[4], pB[4];

    const __nv_bfloat16* Abase_h = Ah + (size_t)(row0 + arow) * Kd + aks;
    const __nv_bfloat16* Abase_l = Al + (size_t)(row0 + arow) * Kd + aks;
    const int bcol = col0 + bnc;

    auto loadA = [&](int s) {
        const __nv_bfloat16* pa = Abase_h + s * 32;
        pA[0] = *(const uint4*)pa; pA[1] = *(const uint4*)(pa + 8);
        const __nv_bfloat16* pl = Abase_l + s * 32;
        pA[2] = *(const uint4*)pl; pA[3] = *(const uint4*)(pl + 8);
    };
    auto loadB = [&](int s) {
        const __nv_bfloat16* pbh = Bh + (size_t)(s * 32 + bkr) * N + bcol;
        const __nv_bfloat16* pbl = Bl + (size_t)(s * 32 + bkr) * N + bcol;
#pragma unroll
        for (int g = 0; g < 2; g++) {
            if (bcol + g*8 + 7 < N) {
                pB[g]   = *(const uint4*)(pbh + g*8);
                pB[2+g] = *(const uint4*)(pbl + g*8);
            } else {
                __nv_bfloat16 th[8], tl[8];
#pragma unroll
                for (int j = 0; j < 8; j++) {
                    bool ok = (bcol + g*8 + j < N);
                    th[j] = ok ? pbh[g*8 + j] : __nv_bfloat16(0.f);
                    tl[j] = ok ? pbl[g*8 + j] : __nv_bfloat16(0.f);
                }
                pB[g]   = *(const uint4*)th;
                pB[2+g] = *(const uint4*)tl;
            }
        }
    };
    auto storeS = [&](int buf) {
        *(uint4*)&As[((buf*2 + 0)*64 + arow)*AS_STRIDE + aks]     = pA[0];
        *(uint4*)&As[((buf*2 + 0)*64 + arow)*AS_STRIDE + aks + 8] = pA[1];
        *(uint4*)&As[((buf*2 + 1)*64 + arow)*AS_STRIDE + aks]     = pA[2];
        *(uint4*)&As[((buf*2 + 1)*64 + arow)*AS_STRIDE + aks + 8] = pA[3];
        *(uint4*)&Bs[((buf*2 + 0)*32 + bkr)*BS_STRIDE + bnc]     = pB[0];
        *(uint4*)&Bs[((buf*2 + 0)*32 + bkr)*BS_STRIDE + bnc + 8] = pB[1];
        *(uint4*)&Bs[((buf*2 + 1)*32 + bkr)*BS_STRIDE + bnc]     = pB[2];
        *(uint4*)&Bs[((buf*2 + 1)*32 + bkr)*BS_STRIDE + bnc + 8] = pB[3];
    };

    const int afr = m0 + (lane & 15);
    const int afc = (lane >> 4) * 8;
    const int bfr = (lane & 15);
    const int bfc = n0 + (lane >> 4) * 8;

    loadB(0);        // static weights: overlap predecessor tail
    PDL_WAIT();      // activations (A) now safe to read
    loadA(0);
    storeS(0);
    __syncthreads();

    for (int s = 0; s < S; s++) {
        const int cur = s & 1;
        if (s + 1 < S) { loadA(s + 1); loadB(s + 1); }

#pragma unroll
        for (int kf = 0; kf < 2; kf++) {
            uint32_t ahr[2][4], alr[2][4], bhr[2][4], blr[2][4];
#pragma unroll
            for (int im = 0; im < 2; im++) {
                uint32_t ad_h = sptr(&As[((cur*2+0)*64 + afr + im*16)*AS_STRIDE + kf*16 + afc]);
                LDSM_X4(ahr[im], ad_h);
                uint32_t ad_l = sptr(&As[((cur*2+1)*64 + afr + im*16)*AS_STRIDE + kf*16 + afc]);
                LDSM_X4(alr[im], ad_l);
            }
#pragma unroll
            for (int nb = 0; nb < 2; nb++) {
                uint32_t bd_h = sptr(&Bs[((cur*2+0)*32 + kf*16 + bfr)*BS_STRIDE + bfc + nb*16]);
                LDSM_X4T(bhr[nb], bd_h);
                uint32_t bd_l = sptr(&Bs[((cur*2+1)*32 + kf*16 + bfr)*BS_STRIDE + bfc + nb*16]);
                LDSM_X4T(blr[nb], bd_l);
            }
#pragma unroll
            for (int im = 0; im < 2; im++)
#pragma unroll
                for (int in = 0; in < 4; in++) {
                    const int nb = in >> 1, ns = in & 1;
                    uint32_t b0h = bhr[nb][ns*2], b1h = bhr[nb][ns*2+1];
                    uint32_t b0l = blr[nb][ns*2], b1l = blr[nb][ns*2+1];
                    MMA_BF16(acc[im][in], ahr[im], b0h, b1h);
                    MMA_BF16(acc[im][in], ahr[im], b0l, b1l);
                    MMA_BF16(acc[im][in], alr[im], b0h, b1h);
                }
        }

        if (s + 1 < S) storeS((s + 1) & 1);
        __syncthreads();
    }

    PDL_TRIGGER();   // mainloop done; successor may schedule during epilogue

    float rp[2][2] = {{0.f, 0.f}, {0.f, 0.f}};   // [im][half] rscore partials

#pragma unroll
    for (int im = 0; im < 2; im++)
#pragma unroll
        for (int in = 0; in < 4; in++) {
            int r = row0 + m0 + im*16 + (lane >> 2);
            int c = col0 + n0 + in*8 + (lane & 3) * 2;
            float bi0 = (c < N)     ? bias[c]     : 0.f;
            float bi1 = (c + 1 < N) ? bias[c + 1] : 0.f;
#pragma unroll
            for (int half = 0; half < 2; half++) {
                int rr = r + half * 8;
                float v0 = acc[im][in][half*2 + 0] + bi0;
                float v1 = acc[im][in][half*2 + 1] + bi1;
                if (EPI == 1) {
                    v0 = fmaxf(v0, 0.f); v1 = fmaxf(v1, 0.f);
                    __nv_bfloat16 h0 = __float2bfloat16(v0);
                    __nv_bfloat16 h1 = __float2bfloat16(v1);
                    __nv_bfloat162 hh; hh.x = h0; hh.y = h1;
                    *(__nv_bfloat162*)&Ch[(size_t)rr*N + c] = hh;
                    __nv_bfloat162 ll;
                    ll.x = __float2bfloat16(v0 - __bfloat162float(h0));
                    ll.y = __float2bfloat16(v1 - __bfloat162float(h1));
                    *(__nv_bfloat162*)&Cl[(size_t)rr*N + c] = ll;
                } else {
                    v0 = 1.f / (1.f + __expf(-v0));
                    v1 = 1.f / (1.f + __expf(-v1));
                    int b = rr / NOUT;
                    if (c < N) {
                        Cf[(size_t)rr*N + c] = v0;
                        float d = xin[(size_t)b*PIX + c] - v0;
                        rp[im][half] += d * d;
                    }
                    if (c + 1 < N) {
                        Cf[(size_t)rr*N + c + 1] = v1;
                        float d = xin[(size_t)b*PIX + c + 1] - v1;
                        rp[im][half] += d * d;
                    }
                }
            }
        }

    if (EPI == 2) {
        // fixed-order reduction: quad shfl -> smem[row][n-half] -> sum
#pragma unroll
        for (int im = 0; im < 2; im++)
#pragma unroll
            for (int half = 0; half < 2; half++) {
                float s = rp[im][half];
                s += __shfl_xor_sync(0xffffffffu, s, 1);
                s += __shfl_xor_sync(0xffffffffu, s, 2);
                if ((lane & 3) == 0)
                    s_rs[m0 + im*16 + half*8 + (lane >> 2)][warp >> 1] = s;
            }
        __syncthreads();
        if (tid < 64)
            g_rsp[blockIdx.x*BN + row0 + tid] = s_rs[tid][0] + s_rs[tid][1];
    }
}

// ---- host-side PDL launcher ----
template <typename F, typename... Args>
static void launch_pdl(F kern, dim3 grid, dim3 block, size_t smem, Args... args) {
    cudaLaunchConfig_t cfg = {};
    cfg.gridDim = grid; cfg.blockDim = block;
    cfg.dynamicSmemBytes = smem; cfg.stream = 0;
    cudaLaunchAttribute at[1];
    at[0].id = cudaLaunchAttributeProgrammaticStreamSerialization;
    at[0].val.programmaticStreamSerializationAllowed = 1;
    cfg.attrs = at; cfg.numAttrs = 1;
    cudaLaunchKernelEx(&cfg, kern, args...);
}

extern "C" void kernel_launch(void* const* d_in, const int* in_sizes, int n_in,
                              void* d_out, int out_size) {
    const float* incaps = (const float*)d_in[0];
    const float* x      = (const float*)d_in[1];
    const float* weight = (const float*)d_in[2];
    const float* W1     = (const float*)d_in[3];
    const float* b1     = (const float*)d_in[4];
    const float* W2     = (const float*)d_in[5];
    const float* b2     = (const float*)d_in[6];
    const float* W3     = (const float*)d_in[7];
    const float* b3     = (const float*)d_in[8];
    float* out = (float*)d_out;

    cudaFuncSetAttribute(k_gemm_tc<1>, cudaFuncAttributeMaxDynamicSharedMemorySize, GEMM_SMEM);
    cudaFuncSetAttribute(k_gemm_tc<2>, cudaFuncAttributeMaxDynamicSharedMemorySize, GEMM_SMEM);
    cudaFuncSetAttribute(k_routing2, cudaFuncAttributeMaxDynamicSharedMemorySize, RT_SMEM);
    cudaFuncSetAttribute(k_hat_split, cudaFuncAttributeMaxDynamicSharedMemorySize, HAT_SMEM);

    __nv_bfloat16 *pW2h, *pW2l, *pW3h, *pW3l, *ph1h, *ph1l, *ph2h, *ph2l;
    float *p_recon;
    cudaGetSymbolAddress((void**)&pW2h, g_W2h);
    cudaGetSymbolAddress((void**)&pW2l, g_W2l);
    cudaGetSymbolAddress((void**)&pW3h, g_W3h);
    cudaGetSymbolAddress((void**)&pW3l, g_W3l);
    cudaGetSymbolAddress((void**)&ph1h, g_h1h);
    cudaGetSymbolAddress((void**)&ph1l, g_h1l);
    cudaGetSymbolAddress((void**)&ph2h, g_h2h);
    cudaGetSymbolAddress((void**)&ph2l, g_h2l);
    cudaGetSymbolAddress((void**)&p_recon, g_recon);

    // first kernel: NO PDL attribute (must serialize against prior graph replay)
    k_hat_split<<<HAT_BLOCKS + SPLIT_BLOCKS, 256, HAT_SMEM>>>(incaps, weight, W2, W3);

    for (int it = 0; it < 2; it++) {
        launch_pdl(k_routing2, dim3(BN), dim3(RT_THREADS), (size_t)RT_SMEM,
                   it > 0 ? 1 : 0, 1, (float*)nullptr, W1, b1);
        launch_pdl(k_scale_c, dim3((BATCH*NIN + 255)/256), dim3(256), (size_t)0);
        launch_pdl(k_gemm_tc<1>, dim3(H2/64, BN/64), dim3(128), (size_t)GEMM_SMEM,
                   (const __nv_bfloat16*)ph1h, (const __nv_bfloat16*)ph1l,
                   (const __nv_bfloat16*)pW2h, (const __nv_bfloat16*)pW2l,
                   b2, (float*)nullptr, ph2h, ph2l, (const float*)nullptr, H2, H1);
        launch_pdl(k_gemm_tc<2>, dim3(NCB2, BN/64), dim3(128), (size_t)GEMM_SMEM,
                   (const __nv_bfloat16*)ph2h, (const __nv_bfloat16*)ph2l,
                   (const __nv_bfloat16*)pW3h, (const __nv_bfloat16*)pW3l,
                   b3, p_recon, (__nv_bfloat16*)nullptr, (__nv_bfloat16*)nullptr,
                   x, PIX, H2);
    }
    launch_pdl(k_routing2, dim3(BN), dim3(RT_THREADS), (size_t)0,
               1, 0, out, W1, b1);
}